// round 11
// baseline (speedup 1.0000x reference)
#include <cuda_runtime.h>
#include <cstdint>
#include <cstddef>

#define FULLMASK 0xffffffffu

constexpr int B_   = 4;
constexpr int N_   = 8192;
constexpr int CIN  = 128;
constexpr int COUT = 256;
constexpr int KNNK = 32;
constexpr int NW   = 4;
constexpr int ROWS = B_ * N_;          // 32768
constexpr int KDIM = NW * CIN;         // 512

// ---------------- scratch (static device globals; no allocation) ----------------
__device__ float4 g_xyzw[ROWS];                         // (x,y,z,|x|^2) packed per point
__device__ float  g_feats[(size_t)ROWS * CIN];          // mean neighbor features
__device__ float  g_aw[ROWS * NW];                      // adaptive weights
__device__ float  g_parts[256 * COUT];                  // BN partial sums
__device__ float  g_partq[256 * COUT];                  // BN partial sums of squares
__device__ float  g_scale[COUT];
__device__ float  g_shift[COUT];

// ---------------- helpers ----------------
static __device__ __forceinline__ float wsum(float v) {
    #pragma unroll
    for (int o = 16; o > 0; o >>= 1) v += __shfl_xor_sync(FULLMASK, v, o);
    return v;
}

// ---------------- 1) pack xyz + squared norm ----------------
// EXPERIMENT E3: DESCENDING fma chain for sq:
//   sq = fma(x,x, fma(y,y, rn(z*z)))
__global__ void prep_kernel(const float* __restrict__ xyz) {
    int gid = blockIdx.x * blockDim.x + threadIdx.x;
    if (gid >= ROWS) return;
    float x = xyz[gid * 3 + 0];
    float y = xyz[gid * 3 + 1];
    float z = xyz[gid * 3 + 2];
    float sq = __fmaf_rn(x, x, __fmaf_rn(y, y, __fmul_rn(z, z)));
    g_xyzw[gid] = make_float4(x, y, z, sq);
}

// ---------------- 2) warp-per-query KNN + geo MLP + softmax + feature mean ----------------
__global__ void __launch_bounds__(256) knn_kernel(
    const float* __restrict__ points,
    const float* __restrict__ W1, const float* __restrict__ b1,
    const float* __restrict__ W2, const float* __restrict__ b2)
{
    int gw   = (blockIdx.x * blockDim.x + threadIdx.x) >> 5;   // warp id = query id
    int lane = threadIdx.x & 31;
    if (gw >= ROWS) return;
    int b = gw >> 13;               // / 8192
    int q = gw & (N_ - 1);

    const float4* cand = g_xyzw + (size_t)b * N_;
    float4 self = cand[q];
    const float qx = self.x, qy = self.y, qz = self.z, qs = self.w;

    const float INF = __int_as_float(0x7f800000);
    // warp-distributed sorted top-K: lane l holds the l-th smallest (dist, idx)
    float ld  = INF;
    int   li  = 0;
    float tau = INF;                // current 32nd smallest (strict threshold)

    for (int base = 0; base < N_; base += 32) {
        float4 c = __ldg(&cand[base + lane]);
        // base ascending fma dot: dot = fma(z,z', fma(y,y', rn(x*x')))
        float dot = __fmul_rn(qx, c.x);
        dot = __fmaf_rn(qy, c.y, dot);
        dot = __fmaf_rn(qz, c.z, dot);
        // base combine: d = ((-2*dot) + sq_m) + sq_n
        float d = __fadd_rn(__fadd_rn(__fmul_rn(-2.0f, dot), qs), c.w);

        // stable-low tie policy (stable top_k: lower index kept on ties)
        unsigned m = __ballot_sync(FULLMASK, d < tau);
        while (m) {
            int src = __ffs(m) - 1;
            m &= m - 1;
            float dc = __shfl_sync(FULLMASK, d, src);
            if (dc < tau) {                       // tau may have tightened; uniform branch
                int ic = base + src;
                // insert AFTER equal values (lower index first)
                unsigned le = __ballot_sync(FULLMASK, ld <= dc);
                int pos = __popc(le);
                float pd = __shfl_up_sync(FULLMASK, ld, 1);
                int   pi = __shfl_up_sync(FULLMASK, li, 1);
                if (lane == pos)      { ld = dc; li = ic; }
                else if (lane > pos)  { ld = pd; li = pi; }
                tau = __shfl_sync(FULLMASK, ld, 31);
            }
        }
    }

    // ---- geo mean of relative neighbor coords ----
    float4 nb = cand[li];
    float gx = wsum(__fadd_rn(nb.x, -qx)) * (1.0f / 32.0f);
    float gy = wsum(__fadd_rn(nb.y, -qy)) * (1.0f / 32.0f);
    float gz = wsum(__fadd_rn(nb.z, -qz)) * (1.0f / 32.0f);

    // ---- tiny MLP: 3 -> 64 (relu) -> 4, distributed over lanes ----
    float a0 = 0.f, a1 = 0.f, a2 = 0.f, a3 = 0.f;
    #pragma unroll
    for (int t = 0; t < 2; ++t) {
        int j = lane + t * 32;
        float h = __ldg(&b1[j]);
        h = __fmaf_rn(gx, __ldg(&W1[j]),        h);
        h = __fmaf_rn(gy, __ldg(&W1[64 + j]),   h);
        h = __fmaf_rn(gz, __ldg(&W1[128 + j]),  h);
        h = fmaxf(h, 0.0f);
        a0 = __fmaf_rn(h, __ldg(&W2[j * 4 + 0]), a0);
        a1 = __fmaf_rn(h, __ldg(&W2[j * 4 + 1]), a1);
        a2 = __fmaf_rn(h, __ldg(&W2[j * 4 + 2]), a2);
        a3 = __fmaf_rn(h, __ldg(&W2[j * 4 + 3]), a3);
    }
    a0 = wsum(a0) + __ldg(&b2[0]);
    a1 = wsum(a1) + __ldg(&b2[1]);
    a2 = wsum(a2) + __ldg(&b2[2]);
    a3 = wsum(a3) + __ldg(&b2[3]);
    float mx = fmaxf(fmaxf(a0, a1), fmaxf(a2, a3));
    float e0 = expf(a0 - mx), e1 = expf(a1 - mx), e2 = expf(a2 - mx), e3 = expf(a3 - mx);
    float inv = 1.0f / (e0 + e1 + e2 + e3);
    if (lane < 4) {
        float v = (lane == 0) ? e0 : (lane == 1) ? e1 : (lane == 2) ? e2 : e3;
        g_aw[gw * 4 + lane] = v * inv;
    }

    // ---- neighbor feature mean: lane handles 4 channels across all 32 neighbors ----
    const float* prow = points + (size_t)b * N_ * CIN;
    float4 acc = make_float4(0.f, 0.f, 0.f, 0.f);
    #pragma unroll 4
    for (int k = 0; k < KNNK; ++k) {
        int ik = __shfl_sync(FULLMASK, li, k);
        float4 p = __ldg((const float4*)(prow + (size_t)ik * CIN) + lane);
        acc.x += p.x; acc.y += p.y; acc.z += p.z; acc.w += p.w;
    }
    float4* fr = (float4*)(g_feats + (size_t)gw * CIN);
    fr[lane] = make_float4(acc.x * (1.0f / 32.0f), acc.y * (1.0f / 32.0f),
                           acc.z * (1.0f / 32.0f), acc.w * (1.0f / 32.0f));
}

// ---------------- 3) fused GEMM: out = [aw (x) feats] (32768 x 512) @ kernels(512 x 256) ----
// plain fp32 (R4 proved the reference GEMM is fp32-exact, not TF32)
constexpr int GBM = 128, GBN = 128, GBK = 16;

__global__ void __launch_bounds__(256) gemm_kernel(
    const float* __restrict__ kern, float* __restrict__ out)
{
    __shared__ float As[GBK][GBM + 4];
    __shared__ float Bs[GBK][GBN];

    int tid = threadIdx.x;
    int tx  = tid & 15;
    int ty  = tid >> 4;
    int m0  = blockIdx.x * GBM;
    int n0  = blockIdx.y * GBN;

    int arow = tid >> 2;          // 0..63
    int acol = (tid & 3) * 4;     // 0,4,8,12
    int brow = tid >> 5;          // 0..7
    int bcol = (tid & 31) * 4;    // 0..124

    float cacc[8][8];
    #pragma unroll
    for (int i = 0; i < 8; ++i)
        #pragma unroll
        for (int j = 0; j < 8; ++j) cacc[i][j] = 0.f;

    for (int kb = 0; kb < KDIM; kb += GBK) {
        int w  = kb >> 7;      // which adaptive kernel
        int c0 = kb & 127;     // channel offset
        #pragma unroll
        for (int r = 0; r < 2; ++r) {
            int m = arow + r * 64;
            float a  = __ldg(&g_aw[(m0 + m) * 4 + w]);
            float4 f = *(const float4*)&g_feats[(size_t)(m0 + m) * CIN + c0 + acol];
            As[acol + 0][m] = f.x * a;
            As[acol + 1][m] = f.y * a;
            As[acol + 2][m] = f.z * a;
            As[acol + 3][m] = f.w * a;
        }
        #pragma unroll
        for (int r = 0; r < 2; ++r) {
            int k = brow + r * 8;
            *(float4*)&Bs[k][bcol] = *(const float4*)&kern[(size_t)(kb + k) * COUT + n0 + bcol];
        }
        __syncthreads();

        #pragma unroll
        for (int kk = 0; kk < GBK; ++kk) {
            float ra[8], rb[8];
            *(float4*)(ra)     = *(const float4*)&As[kk][ty * 8];
            *(float4*)(ra + 4) = *(const float4*)&As[kk][ty * 8 + 4];
            *(float4*)(rb)     = *(const float4*)&Bs[kk][tx * 8];
            *(float4*)(rb + 4) = *(const float4*)&Bs[kk][tx * 8 + 4];
            #pragma unroll
            for (int i = 0; i < 8; ++i)
                #pragma unroll
                for (int j = 0; j < 8; ++j)
                    cacc[i][j] = __fmaf_rn(ra[i], rb[j], cacc[i][j]);
        }
        __syncthreads();
    }

    #pragma unroll
    for (int i = 0; i < 8; ++i) {
        size_t row = (size_t)(m0 + ty * 8 + i) * COUT + n0 + tx * 8;
        *(float4*)&out[row]     = make_float4(cacc[i][0], cacc[i][1], cacc[i][2], cacc[i][3]);
        *(float4*)&out[row + 4] = make_float4(cacc[i][4], cacc[i][5], cacc[i][6], cacc[i][7]);
    }
}

// ---------------- 4) BatchNorm (deterministic two-stage reduction) ----------------
__global__ void bn_reduce(const float* __restrict__ out) {
    int o = threadIdx.x;                       // channel
    size_t r0 = (size_t)blockIdx.x * 128;
    const float* p = out + r0 * COUT + o;
    float s = 0.f, s2 = 0.f;
    #pragma unroll 4
    for (int r = 0; r < 128; ++r) {
        float v = p[(size_t)r * COUT];
        s += v;
        s2 = __fmaf_rn(v, v, s2);
    }
    g_parts[blockIdx.x * COUT + o] = s;
    g_partq[blockIdx.x * COUT + o] = s2;
}

__global__ void bn_final(const float* __restrict__ gamma, const float* __restrict__ beta) {
    int o = threadIdx.x;
    float s = 0.f, s2 = 0.f;
    for (int i = 0; i < 256; ++i) {
        s  += g_parts[i * COUT + o];
        s2 += g_partq[i * COUT + o];
    }
    float mu  = s  * (1.0f / (float)ROWS);
    float var = s2 * (1.0f / (float)ROWS) - mu * mu;
    float sc  = gamma[o] * rsqrtf(var + 1e-5f);
    g_scale[o] = sc;
    g_shift[o] = __fmaf_rn(-mu, sc, beta[o]);
}

__global__ void bn_apply(float* __restrict__ out) {
    int f = blockIdx.x * blockDim.x + threadIdx.x;   // float4 index
    float4 v = ((float4*)out)[f];
    int c4 = f & 63;                                  // 256 channels / 4
    float4 sc = ((const float4*)g_scale)[c4];
    float4 sh = ((const float4*)g_shift)[c4];
    v.x = __fmaf_rn(v.x, sc.x, sh.x);
    v.y = __fmaf_rn(v.y, sc.y, sh.y);
    v.z = __fmaf_rn(v.z, sc.z, sh.z);
    v.w = __fmaf_rn(v.w, sc.w, sh.w);
    ((float4*)out)[f] = v;
}

// ---------------- launch ----------------
extern "C" void kernel_launch(void* const* d_in, const int* in_sizes, int n_in,
                              void* d_out, int out_size)
{
    (void)in_sizes; (void)n_in; (void)out_size;
    const float* xyz    = (const float*)d_in[0];
    const float* points = (const float*)d_in[1];
    const float* W1     = (const float*)d_in[2];
    const float* b1     = (const float*)d_in[3];
    const float* W2     = (const float*)d_in[4];
    const float* b2     = (const float*)d_in[5];
    const float* kern   = (const float*)d_in[6];
    const float* gamma  = (const float*)d_in[7];
    const float* beta   = (const float*)d_in[8];
    float* out = (float*)d_out;

    prep_kernel<<<ROWS / 256, 256>>>(xyz);
    knn_kernel<<<(ROWS * 32) / 256, 256>>>(points, W1, b1, W2, b2);
    gemm_kernel<<<dim3(ROWS / GBM, COUT / GBN), 256>>>(kern, out);
    bn_reduce<<<256, 256>>>(out);
    bn_final<<<1, 256>>>(gamma, beta);
    bn_apply<<<(ROWS * COUT / 4) / 256, 256>>>(out);
}

// round 12
// speedup vs baseline: 1.2120x; 1.2120x over previous
#include <cuda_runtime.h>
#include <cstdint>
#include <cstddef>

#define FULLMASK 0xffffffffu

constexpr int B_   = 4;
constexpr int N_   = 8192;
constexpr int CIN  = 128;
constexpr int COUT = 256;
constexpr int KNNK = 32;
constexpr int NW   = 4;
constexpr int ROWS = B_ * N_;          // 32768
constexpr int KDIM = NW * CIN;         // 512

// ---------------- scratch (static device globals; no allocation) ----------------
__device__ float4 g_xyzw[ROWS];                         // (x,y,z,|x|^2) packed per point
__device__ float  g_feats[(size_t)ROWS * CIN];          // mean neighbor features
__device__ float  g_aw[ROWS * NW];                      // adaptive weights
__device__ float  g_parts[512 * COUT];                  // BN partial sums
__device__ float  g_partq[512 * COUT];                  // BN partial sums of squares
__device__ float  g_scale[COUT];
__device__ float  g_shift[COUT];

// ---------------- helpers ----------------
static __device__ __forceinline__ float wsum(float v) {
    #pragma unroll
    for (int o = 16; o > 0; o >>= 1) v += __shfl_xor_sync(FULLMASK, v, o);
    return v;
}

// TF32 input rounding (round-nearest-away), as used by cuBLAS tensor-core GEMMs
static __device__ __forceinline__ float tf32r(float x) {
    uint32_t u;
    asm("cvt.rna.tf32.f32 %0, %1;" : "=r"(u) : "f"(x));
    return __uint_as_float(u);
}

static __device__ __forceinline__ void mma_tf32(float c[4], const uint32_t a[4],
                                                const uint32_t b[2]) {
    asm volatile(
        "mma.sync.aligned.m16n8k8.row.col.f32.tf32.tf32.f32 "
        "{%0,%1,%2,%3}, {%4,%5,%6,%7}, {%8,%9}, {%0,%1,%2,%3};\n"
        : "+f"(c[0]), "+f"(c[1]), "+f"(c[2]), "+f"(c[3])
        : "r"(a[0]), "r"(a[1]), "r"(a[2]), "r"(a[3]), "r"(b[0]), "r"(b[1]));
}

// ---------------- 1) pack xyz + squared norm (CERTIFIED — do not modify) --------
// sq = fma(x,x, fma(y,y, rn(z*z)))   [R11: this matches the reference bitwise]
__global__ void prep_kernel(const float* __restrict__ xyz) {
    int gid = blockIdx.x * blockDim.x + threadIdx.x;
    if (gid >= ROWS) return;
    float x = xyz[gid * 3 + 0];
    float y = xyz[gid * 3 + 1];
    float z = xyz[gid * 3 + 2];
    float sq = __fmaf_rn(x, x, __fmaf_rn(y, y, __fmul_rn(z, z)));
    g_xyzw[gid] = make_float4(x, y, z, sq);
}

// ---------------- 2) warp-per-query KNN + geo MLP + softmax + feature mean -------
// (CERTIFIED arithmetic — distance + selection untouched from R11)
__global__ void __launch_bounds__(256) knn_kernel(
    const float* __restrict__ points,
    const float* __restrict__ W1, const float* __restrict__ b1,
    const float* __restrict__ W2, const float* __restrict__ b2)
{
    int gw   = (blockIdx.x * blockDim.x + threadIdx.x) >> 5;   // warp id = query id
    int lane = threadIdx.x & 31;
    if (gw >= ROWS) return;
    int b = gw >> 13;               // / 8192
    int q = gw & (N_ - 1);

    const float4* cand = g_xyzw + (size_t)b * N_;
    float4 self = cand[q];
    const float qx = self.x, qy = self.y, qz = self.z, qs = self.w;

    const float INF = __int_as_float(0x7f800000);
    float ld  = INF;
    int   li  = 0;
    float tau = INF;

    for (int base = 0; base < N_; base += 32) {
        float4 c = __ldg(&cand[base + lane]);
        float dot = __fmul_rn(qx, c.x);
        dot = __fmaf_rn(qy, c.y, dot);
        dot = __fmaf_rn(qz, c.z, dot);
        float d = __fadd_rn(__fadd_rn(__fmul_rn(-2.0f, dot), qs), c.w);

        unsigned m = __ballot_sync(FULLMASK, d < tau);
        while (m) {
            int src = __ffs(m) - 1;
            m &= m - 1;
            float dc = __shfl_sync(FULLMASK, d, src);
            if (dc < tau) {
                int ic = base + src;
                unsigned le = __ballot_sync(FULLMASK, ld <= dc);
                int pos = __popc(le);
                float pd = __shfl_up_sync(FULLMASK, ld, 1);
                int   pi = __shfl_up_sync(FULLMASK, li, 1);
                if (lane == pos)      { ld = dc; li = ic; }
                else if (lane > pos)  { ld = pd; li = pi; }
                tau = __shfl_sync(FULLMASK, ld, 31);
            }
        }
    }

    // ---- geo mean of relative neighbor coords ----
    float4 nb = cand[li];
    float gx = wsum(__fadd_rn(nb.x, -qx)) * (1.0f / 32.0f);
    float gy = wsum(__fadd_rn(nb.y, -qy)) * (1.0f / 32.0f);
    float gz = wsum(__fadd_rn(nb.z, -qz)) * (1.0f / 32.0f);

    // ---- tiny MLP: 3 -> 64 (relu) -> 4 ----
    float a0 = 0.f, a1 = 0.f, a2 = 0.f, a3 = 0.f;
    #pragma unroll
    for (int t = 0; t < 2; ++t) {
        int j = lane + t * 32;
        float h = __ldg(&b1[j]);
        h = __fmaf_rn(gx, __ldg(&W1[j]),        h);
        h = __fmaf_rn(gy, __ldg(&W1[64 + j]),   h);
        h = __fmaf_rn(gz, __ldg(&W1[128 + j]),  h);
        h = fmaxf(h, 0.0f);
        a0 = __fmaf_rn(h, __ldg(&W2[j * 4 + 0]), a0);
        a1 = __fmaf_rn(h, __ldg(&W2[j * 4 + 1]), a1);
        a2 = __fmaf_rn(h, __ldg(&W2[j * 4 + 2]), a2);
        a3 = __fmaf_rn(h, __ldg(&W2[j * 4 + 3]), a3);
    }
    a0 = wsum(a0) + __ldg(&b2[0]);
    a1 = wsum(a1) + __ldg(&b2[1]);
    a2 = wsum(a2) + __ldg(&b2[2]);
    a3 = wsum(a3) + __ldg(&b2[3]);
    float mx = fmaxf(fmaxf(a0, a1), fmaxf(a2, a3));
    float e0 = expf(a0 - mx), e1 = expf(a1 - mx), e2 = expf(a2 - mx), e3 = expf(a3 - mx);
    float inv = 1.0f / (e0 + e1 + e2 + e3);
    if (lane < 4) {
        float v = (lane == 0) ? e0 : (lane == 1) ? e1 : (lane == 2) ? e2 : e3;
        g_aw[gw * 4 + lane] = v * inv;
    }

    // ---- neighbor feature mean ----
    const float* prow = points + (size_t)b * N_ * CIN;
    float4 acc = make_float4(0.f, 0.f, 0.f, 0.f);
    #pragma unroll 4
    for (int k = 0; k < KNNK; ++k) {
        int ik = __shfl_sync(FULLMASK, li, k);
        float4 p = __ldg((const float4*)(prow + (size_t)ik * CIN) + lane);
        acc.x += p.x; acc.y += p.y; acc.z += p.z; acc.w += p.w;
    }
    float4* fr = (float4*)(g_feats + (size_t)gw * CIN);
    fr[lane] = make_float4(acc.x * (1.0f / 32.0f), acc.y * (1.0f / 32.0f),
                           acc.z * (1.0f / 32.0f), acc.w * (1.0f / 32.0f));
}

// ---------------- 3) TF32 tensor-core GEMM ----------------
// out = [aw (x) feats] (32768 x 512) @ kernels(512 x 256)
// TF32 inputs (cvt.rna), fp32 accumulate — error budget measured in R4: ~3e-4.
constexpr int TBM = 128, TBN = 128, TBK = 32;
constexpr int APAD = 36;    // banks (4*gid+tig) unique
constexpr int BPAD = 136;   // banks (8*tig+gid) unique

__global__ void __launch_bounds__(256) gemm_tc(
    const float* __restrict__ kern, float* __restrict__ out)
{
    __shared__ float As[TBM][APAD];
    __shared__ float Bs[TBK][BPAD];

    int tid  = threadIdx.x;
    int warp = tid >> 5, lane = tid & 31;
    int wm = warp & 1;            // 0..1  -> 64-row slice
    int wn = warp >> 1;           // 0..3  -> 32-col slice
    int gid = lane >> 2, tig = lane & 3;
    int m0 = blockIdx.x * TBM, n0 = blockIdx.y * TBN;

    float acc[4][4][4];
    #pragma unroll
    for (int i = 0; i < 4; ++i)
        #pragma unroll
        for (int j = 0; j < 4; ++j)
            #pragma unroll
            for (int r = 0; r < 4; ++r) acc[i][j][r] = 0.f;

    int arow = tid >> 1, acc0 = (tid & 1) * 16;       // A stage: 2 thr/row, 16 cols each
    int brow = tid >> 3, bcc0 = (tid & 7) * 16;       // B stage: 8 thr/row, 16 cols each

    for (int kb = 0; kb < KDIM; kb += TBK) {
        int w  = kb >> 7;
        int c0 = kb & 127;
        // stage A = tf32(aw * feats)
        {
            float a = __ldg(&g_aw[(m0 + arow) * 4 + w]);
            const float* fp = &g_feats[(size_t)(m0 + arow) * CIN + c0 + acc0];
            #pragma unroll
            for (int u = 0; u < 4; ++u) {
                float4 f = *(const float4*)(fp + u * 4);
                float4 v = make_float4(tf32r(f.x * a), tf32r(f.y * a),
                                       tf32r(f.z * a), tf32r(f.w * a));
                *(float4*)&As[arow][acc0 + u * 4] = v;
            }
        }
        // stage B = tf32(kern)
        {
            const float* bp = &kern[(size_t)(kb + brow) * COUT + n0 + bcc0];
            #pragma unroll
            for (int u = 0; u < 4; ++u) {
                float4 f = *(const float4*)(bp + u * 4);
                float4 v = make_float4(tf32r(f.x), tf32r(f.y), tf32r(f.z), tf32r(f.w));
                *(float4*)&Bs[brow][bcc0 + u * 4] = v;
            }
        }
        __syncthreads();

        #pragma unroll
        for (int ks = 0; ks < 4; ++ks) {
            uint32_t af[4][4];
            #pragma unroll
            for (int mi = 0; mi < 4; ++mi) {
                int r = wm * 64 + mi * 16;
                int c = ks * 8 + tig;
                af[mi][0] = __float_as_uint(As[r + gid    ][c    ]);
                af[mi][1] = __float_as_uint(As[r + gid + 8][c    ]);
                af[mi][2] = __float_as_uint(As[r + gid    ][c + 4]);
                af[mi][3] = __float_as_uint(As[r + gid + 8][c + 4]);
            }
            uint32_t bf[4][2];
            #pragma unroll
            for (int nj = 0; nj < 4; ++nj) {
                int cb = wn * 32 + nj * 8 + gid;
                bf[nj][0] = __float_as_uint(Bs[ks * 8 + tig    ][cb]);
                bf[nj][1] = __float_as_uint(Bs[ks * 8 + tig + 4][cb]);
            }
            #pragma unroll
            for (int mi = 0; mi < 4; ++mi)
                #pragma unroll
                for (int nj = 0; nj < 4; ++nj)
                    mma_tf32(acc[mi][nj], af[mi], bf[nj]);
        }
        __syncthreads();
    }

    // epilogue
    #pragma unroll
    for (int mi = 0; mi < 4; ++mi) {
        #pragma unroll
        for (int nj = 0; nj < 4; ++nj) {
            int r  = m0 + wm * 64 + mi * 16 + gid;
            int cc = n0 + wn * 32 + nj * 8 + 2 * tig;
            *(float2*)&out[(size_t)r * COUT + cc] =
                make_float2(acc[mi][nj][0], acc[mi][nj][1]);
            *(float2*)&out[(size_t)(r + 8) * COUT + cc] =
                make_float2(acc[mi][nj][2], acc[mi][nj][3]);
        }
    }
}

// ---------------- 4) BatchNorm (deterministic two-stage reduction) ----------------
__global__ void bn_reduce(const float* __restrict__ out) {
    int o = threadIdx.x;                       // channel
    size_t r0 = (size_t)blockIdx.x * 64;
    const float* p = out + r0 * COUT + o;
    float s = 0.f, s2 = 0.f;
    #pragma unroll 4
    for (int r = 0; r < 64; ++r) {
        float v = p[(size_t)r * COUT];
        s += v;
        s2 = __fmaf_rn(v, v, s2);
    }
    g_parts[blockIdx.x * COUT + o] = s;
    g_partq[blockIdx.x * COUT + o] = s2;
}

__global__ void bn_final(const float* __restrict__ gamma, const float* __restrict__ beta) {
    int o = threadIdx.x;
    float s = 0.f, s2 = 0.f;
    for (int i = 0; i < 512; ++i) {
        s  += g_parts[i * COUT + o];
        s2 += g_partq[i * COUT + o];
    }
    float mu  = s  * (1.0f / (float)ROWS);
    float var = s2 * (1.0f / (float)ROWS) - mu * mu;
    float sc  = gamma[o] * rsqrtf(var + 1e-5f);
    g_scale[o] = sc;
    g_shift[o] = __fmaf_rn(-mu, sc, beta[o]);
}

__global__ void bn_apply(float* __restrict__ out) {
    int f = blockIdx.x * blockDim.x + threadIdx.x;   // float4 index
    float4 v = ((float4*)out)[f];
    int c4 = f & 63;
    float4 sc = ((const float4*)g_scale)[c4];
    float4 sh = ((const float4*)g_shift)[c4];
    v.x = __fmaf_rn(v.x, sc.x, sh.x);
    v.y = __fmaf_rn(v.y, sc.y, sh.y);
    v.z = __fmaf_rn(v.z, sc.z, sh.z);
    v.w = __fmaf_rn(v.w, sc.w, sh.w);
    ((float4*)out)[f] = v;
}

// ---------------- launch ----------------
extern "C" void kernel_launch(void* const* d_in, const int* in_sizes, int n_in,
                              void* d_out, int out_size)
{
    (void)in_sizes; (void)n_in; (void)out_size;
    const float* xyz    = (const float*)d_in[0];
    const float* points = (const float*)d_in[1];
    const float* W1     = (const float*)d_in[2];
    const float* b1     = (const float*)d_in[3];
    const float* W2     = (const float*)d_in[4];
    const float* b2     = (const float*)d_in[5];
    const float* kern   = (const float*)d_in[6];
    const float* gamma  = (const float*)d_in[7];
    const float* beta   = (const float*)d_in[8];
    float* out = (float*)d_out;

    prep_kernel<<<ROWS / 256, 256>>>(xyz);
    knn_kernel<<<(ROWS * 32) / 256, 256>>>(points, W1, b1, W2, b2);
    gemm_tc<<<dim3(ROWS / TBM, COUT / TBN), 256>>>(kern, out);
    bn_reduce<<<512, 256>>>(out);
    bn_final<<<1, 256>>>(gamma, beta);
    bn_apply<<<(ROWS * COUT / 4) / 256, 256>>>(out);
}

// round 13
// speedup vs baseline: 1.2469x; 1.0288x over previous
#include <cuda_runtime.h>
#include <cstdint>
#include <cstddef>

#define FULLMASK 0xffffffffu

constexpr int B_   = 4;
constexpr int N_   = 8192;
constexpr int CIN  = 128;
constexpr int COUT = 256;
constexpr int KNNK = 32;
constexpr int NW   = 4;
constexpr int ROWS = B_ * N_;          // 32768
constexpr int KDIM = NW * CIN;         // 512
constexpr int QPW  = 4;                // queries per warp

// ---------------- scratch (static device globals; no allocation) ----------------
__device__ float4 g_xyzw[ROWS];
__device__ float  g_feats[(size_t)ROWS * CIN];
__device__ float  g_aw[ROWS * NW];
__device__ float  g_parts[512 * COUT];
__device__ float  g_partq[512 * COUT];
__device__ float  g_scale[COUT];
__device__ float  g_shift[COUT];

// ---------------- helpers ----------------
static __device__ __forceinline__ float wsum(float v) {
    #pragma unroll
    for (int o = 16; o > 0; o >>= 1) v += __shfl_xor_sync(FULLMASK, v, o);
    return v;
}

static __device__ __forceinline__ float tf32r(float x) {
    uint32_t u;
    asm("cvt.rna.tf32.f32 %0, %1;" : "=r"(u) : "f"(x));
    return __uint_as_float(u);
}

static __device__ __forceinline__ void mma_tf32(float c[4], const uint32_t a[4],
                                                const uint32_t b[2]) {
    asm volatile(
        "mma.sync.aligned.m16n8k8.row.col.f32.tf32.tf32.f32 "
        "{%0,%1,%2,%3}, {%4,%5,%6,%7}, {%8,%9}, {%0,%1,%2,%3};\n"
        : "+f"(c[0]), "+f"(c[1]), "+f"(c[2]), "+f"(c[3])
        : "r"(a[0]), "r"(a[1]), "r"(a[2]), "r"(a[3]), "r"(b[0]), "r"(b[1]));
}

// ---------------- 1) pack xyz + squared norm (CERTIFIED — do not modify) --------
// sq = fma(x,x, fma(y,y, rn(z*z)))
__global__ void prep_kernel(const float* __restrict__ xyz) {
    int gid = blockIdx.x * blockDim.x + threadIdx.x;
    if (gid >= ROWS) return;
    float x = xyz[gid * 3 + 0];
    float y = xyz[gid * 3 + 1];
    float z = xyz[gid * 3 + 2];
    float sq = __fmaf_rn(x, x, __fmaf_rn(y, y, __fmul_rn(z, z)));
    g_xyzw[gid] = make_float4(x, y, z, sq);
}

// ---------------- 2) KNN: one warp serves QPW=4 queries --------------------------
// Distance arithmetic + stable-low insertion are bit-identical to the certified
// R11 version; candidates are processed in increasing index order per query.
__global__ void __launch_bounds__(256) knn_kernel(
    const float* __restrict__ points,
    const float* __restrict__ W1, const float* __restrict__ b1,
    const float* __restrict__ W2, const float* __restrict__ b2)
{
    int gw   = (blockIdx.x * blockDim.x + threadIdx.x) >> 5;   // warp id
    int lane = threadIdx.x & 31;
    int wq   = gw * QPW;                    // first query of this warp
    if (wq >= ROWS) return;
    int b = wq >> 13;                       // batch (all QPW queries same batch)

    const float4* cand = g_xyzw + (size_t)b * N_;
    int qbase = wq & (N_ - 1);

    float qx[QPW], qy[QPW], qz[QPW], qs[QPW];
    #pragma unroll
    for (int j = 0; j < QPW; ++j) {
        float4 s = __ldg(&cand[qbase + j]);          // broadcast load
        qx[j] = s.x; qy[j] = s.y; qz[j] = s.z; qs[j] = s.w;
    }

    const float INF = __int_as_float(0x7f800000);
    float ld[QPW]  = {INF, INF, INF, INF};
    int   li[QPW]  = {0, 0, 0, 0};
    float tau[QPW] = {INF, INF, INF, INF};

    #pragma unroll 2
    for (int base = 0; base < N_; base += 32) {
        float4 c = __ldg(&cand[base + lane]);
        float d[QPW];
        #pragma unroll
        for (int j = 0; j < QPW; ++j) {
            // CERTIFIED: dot = fma(z,z', fma(y,y', rn(x*x')))
            float dot = __fmul_rn(qx[j], c.x);
            dot = __fmaf_rn(qy[j], c.y, dot);
            dot = __fmaf_rn(qz[j], c.z, dot);
            // CERTIFIED: d = ((-2*dot) + sq_m) + sq_n
            d[j] = __fadd_rn(__fadd_rn(__fmul_rn(-2.0f, dot), qs[j]), c.w);
        }
        bool hit = (d[0] < tau[0]) | (d[1] < tau[1]) | (d[2] < tau[2]) | (d[3] < tau[3]);
        if (__ballot_sync(FULLMASK, hit)) {
            #pragma unroll
            for (int j = 0; j < QPW; ++j) {
                unsigned m = __ballot_sync(FULLMASK, d[j] < tau[j]);
                while (m) {
                    int src = __ffs(m) - 1;
                    m &= m - 1;
                    float dc = __shfl_sync(FULLMASK, d[j], src);
                    if (dc < tau[j]) {
                        int ic = base + src;
                        // stable-low: insert AFTER equal values
                        unsigned le = __ballot_sync(FULLMASK, ld[j] <= dc);
                        int pos = __popc(le);
                        float pd = __shfl_up_sync(FULLMASK, ld[j], 1);
                        int   pi = __shfl_up_sync(FULLMASK, li[j], 1);
                        if (lane == pos)      { ld[j] = dc; li[j] = ic; }
                        else if (lane > pos)  { ld[j] = pd; li[j] = pi; }
                        tau[j] = __shfl_sync(FULLMASK, ld[j], 31);
                    }
                }
            }
        }
    }

    // ---- per-query epilogue (identical arithmetic to certified version) ----
    const float* prow = points + (size_t)b * N_ * CIN;
    #pragma unroll
    for (int j = 0; j < QPW; ++j) {
        float4 nb = cand[li[j]];
        float gx = wsum(__fadd_rn(nb.x, -qx[j])) * (1.0f / 32.0f);
        float gy = wsum(__fadd_rn(nb.y, -qy[j])) * (1.0f / 32.0f);
        float gz = wsum(__fadd_rn(nb.z, -qz[j])) * (1.0f / 32.0f);

        float a0 = 0.f, a1 = 0.f, a2 = 0.f, a3 = 0.f;
        #pragma unroll
        for (int t = 0; t < 2; ++t) {
            int jj = lane + t * 32;
            float h = __ldg(&b1[jj]);
            h = __fmaf_rn(gx, __ldg(&W1[jj]),        h);
            h = __fmaf_rn(gy, __ldg(&W1[64 + jj]),   h);
            h = __fmaf_rn(gz, __ldg(&W1[128 + jj]),  h);
            h = fmaxf(h, 0.0f);
            a0 = __fmaf_rn(h, __ldg(&W2[jj * 4 + 0]), a0);
            a1 = __fmaf_rn(h, __ldg(&W2[jj * 4 + 1]), a1);
            a2 = __fmaf_rn(h, __ldg(&W2[jj * 4 + 2]), a2);
            a3 = __fmaf_rn(h, __ldg(&W2[jj * 4 + 3]), a3);
        }
        a0 = wsum(a0) + __ldg(&b2[0]);
        a1 = wsum(a1) + __ldg(&b2[1]);
        a2 = wsum(a2) + __ldg(&b2[2]);
        a3 = wsum(a3) + __ldg(&b2[3]);
        float mx = fmaxf(fmaxf(a0, a1), fmaxf(a2, a3));
        float e0 = expf(a0 - mx), e1 = expf(a1 - mx), e2 = expf(a2 - mx), e3 = expf(a3 - mx);
        float inv = 1.0f / (e0 + e1 + e2 + e3);
        if (lane < 4) {
            float v = (lane == 0) ? e0 : (lane == 1) ? e1 : (lane == 2) ? e2 : e3;
            g_aw[(wq + j) * 4 + lane] = v * inv;
        }

        float4 acc = make_float4(0.f, 0.f, 0.f, 0.f);
        #pragma unroll 4
        for (int k = 0; k < KNNK; ++k) {
            int ik = __shfl_sync(FULLMASK, li[j], k);
            float4 p = __ldg((const float4*)(prow + (size_t)ik * CIN) + lane);
            acc.x += p.x; acc.y += p.y; acc.z += p.z; acc.w += p.w;
        }
        float4* fr = (float4*)(g_feats + (size_t)(wq + j) * CIN);
        fr[lane] = make_float4(acc.x * (1.0f / 32.0f), acc.y * (1.0f / 32.0f),
                               acc.z * (1.0f / 32.0f), acc.w * (1.0f / 32.0f));
    }
}

// ---------------- 3) TF32 tensor-core GEMM (unchanged from R12) ------------------
constexpr int TBM = 128, TBN = 128, TBK = 32;
constexpr int APAD = 36;
constexpr int BPAD = 136;

__global__ void __launch_bounds__(256) gemm_tc(
    const float* __restrict__ kern, float* __restrict__ out)
{
    __shared__ float As[TBM][APAD];
    __shared__ float Bs[TBK][BPAD];

    int tid  = threadIdx.x;
    int warp = tid >> 5, lane = tid & 31;
    int wm = warp & 1;
    int wn = warp >> 1;
    int gid = lane >> 2, tig = lane & 3;
    int m0 = blockIdx.x * TBM, n0 = blockIdx.y * TBN;

    float acc[4][4][4];
    #pragma unroll
    for (int i = 0; i < 4; ++i)
        #pragma unroll
        for (int j = 0; j < 4; ++j)
            #pragma unroll
            for (int r = 0; r < 4; ++r) acc[i][j][r] = 0.f;

    int arow = tid >> 1, acc0 = (tid & 1) * 16;
    int brow = tid >> 3, bcc0 = (tid & 7) * 16;

    for (int kb = 0; kb < KDIM; kb += TBK) {
        int w  = kb >> 7;
        int c0 = kb & 127;
        {
            float a = __ldg(&g_aw[(m0 + arow) * 4 + w]);
            const float* fp = &g_feats[(size_t)(m0 + arow) * CIN + c0 + acc0];
            #pragma unroll
            for (int u = 0; u < 4; ++u) {
                float4 f = *(const float4*)(fp + u * 4);
                float4 v = make_float4(tf32r(f.x * a), tf32r(f.y * a),
                                       tf32r(f.z * a), tf32r(f.w * a));
                *(float4*)&As[arow][acc0 + u * 4] = v;
            }
        }
        {
            const float* bp = &kern[(size_t)(kb + brow) * COUT + n0 + bcc0];
            #pragma unroll
            for (int u = 0; u < 4; ++u) {
                float4 f = *(const float4*)(bp + u * 4);
                float4 v = make_float4(tf32r(f.x), tf32r(f.y), tf32r(f.z), tf32r(f.w));
                *(float4*)&Bs[brow][bcc0 + u * 4] = v;
            }
        }
        __syncthreads();

        #pragma unroll
        for (int ks = 0; ks < 4; ++ks) {
            uint32_t af[4][4];
            #pragma unroll
            for (int mi = 0; mi < 4; ++mi) {
                int r = wm * 64 + mi * 16;
                int c = ks * 8 + tig;
                af[mi][0] = __float_as_uint(As[r + gid    ][c    ]);
                af[mi][1] = __float_as_uint(As[r + gid + 8][c    ]);
                af[mi][2] = __float_as_uint(As[r + gid    ][c + 4]);
                af[mi][3] = __float_as_uint(As[r + gid + 8][c + 4]);
            }
            uint32_t bf[4][2];
            #pragma unroll
            for (int nj = 0; nj < 4; ++nj) {
                int cb = wn * 32 + nj * 8 + gid;
                bf[nj][0] = __float_as_uint(Bs[ks * 8 + tig    ][cb]);
                bf[nj][1] = __float_as_uint(Bs[ks * 8 + tig + 4][cb]);
            }
            #pragma unroll
            for (int mi = 0; mi < 4; ++mi)
                #pragma unroll
                for (int nj = 0; nj < 4; ++nj)
                    mma_tf32(acc[mi][nj], af[mi], bf[nj]);
        }
        __syncthreads();
    }

    #pragma unroll
    for (int mi = 0; mi < 4; ++mi) {
        #pragma unroll
        for (int nj = 0; nj < 4; ++nj) {
            int r  = m0 + wm * 64 + mi * 16 + gid;
            int cc = n0 + wn * 32 + nj * 8 + 2 * tig;
            *(float2*)&out[(size_t)r * COUT + cc] =
                make_float2(acc[mi][nj][0], acc[mi][nj][1]);
            *(float2*)&out[(size_t)(r + 8) * COUT + cc] =
                make_float2(acc[mi][nj][2], acc[mi][nj][3]);
        }
    }
}

// ---------------- 4) BatchNorm (deterministic two-stage reduction) ----------------
__global__ void bn_reduce(const float* __restrict__ out) {
    int o = threadIdx.x;
    size_t r0 = (size_t)blockIdx.x * 64;
    const float* p = out + r0 * COUT + o;
    float s = 0.f, s2 = 0.f;
    #pragma unroll 4
    for (int r = 0; r < 64; ++r) {
        float v = p[(size_t)r * COUT];
        s += v;
        s2 = __fmaf_rn(v, v, s2);
    }
    g_parts[blockIdx.x * COUT + o] = s;
    g_partq[blockIdx.x * COUT + o] = s2;
}

__global__ void bn_final(const float* __restrict__ gamma, const float* __restrict__ beta) {
    int o = threadIdx.x;
    float s = 0.f, s2 = 0.f;
    for (int i = 0; i < 512; ++i) {
        s  += g_parts[i * COUT + o];
        s2 += g_partq[i * COUT + o];
    }
    float mu  = s  * (1.0f / (float)ROWS);
    float var = s2 * (1.0f / (float)ROWS) - mu * mu;
    float sc  = gamma[o] * rsqrtf(var + 1e-5f);
    g_scale[o] = sc;
    g_shift[o] = __fmaf_rn(-mu, sc, beta[o]);
}

__global__ void bn_apply(float* __restrict__ out) {
    int f = blockIdx.x * blockDim.x + threadIdx.x;
    float4 v = ((float4*)out)[f];
    int c4 = f & 63;
    float4 sc = ((const float4*)g_scale)[c4];
    float4 sh = ((const float4*)g_shift)[c4];
    v.x = __fmaf_rn(v.x, sc.x, sh.x);
    v.y = __fmaf_rn(v.y, sc.y, sh.y);
    v.z = __fmaf_rn(v.z, sc.z, sh.z);
    v.w = __fmaf_rn(v.w, sc.w, sh.w);
    ((float4*)out)[f] = v;
}

// ---------------- launch ----------------
extern "C" void kernel_launch(void* const* d_in, const int* in_sizes, int n_in,
                              void* d_out, int out_size)
{
    (void)in_sizes; (void)n_in; (void)out_size;
    const float* xyz    = (const float*)d_in[0];
    const float* points = (const float*)d_in[1];
    const float* W1     = (const float*)d_in[2];
    const float* b1     = (const float*)d_in[3];
    const float* W2     = (const float*)d_in[4];
    const float* b2     = (const float*)d_in[5];
    const float* kern   = (const float*)d_in[6];
    const float* gamma  = (const float*)d_in[7];
    const float* beta   = (const float*)d_in[8];
    float* out = (float*)d_out;

    prep_kernel<<<ROWS / 256, 256>>>(xyz);
    knn_kernel<<<(ROWS / QPW) * 32 / 256, 256>>>(points, W1, b1, W2, b2);
    gemm_tc<<<dim3(ROWS / TBM, COUT / TBN), 256>>>(kern, out);
    bn_reduce<<<512, 256>>>(out);
    bn_final<<<1, 256>>>(gamma, beta);
    bn_apply<<<(ROWS * COUT / 4) / 256, 256>>>(out);
}